// round 3
// baseline (speedup 1.0000x reference)
#include <cuda_runtime.h>
#include <cstdint>
#include <cstddef>

typedef unsigned long long ull;

#define Dd 256
#define Tt 1024
#define Bb 64

#define RREG 176
#define NPAIR_REG 88
#define QREG 44
#define NPAIR_SH 40
#define SMEM_FLOW (8192 + NPAIR_SH*Dd*8)

// scratch: W = u @ Bm + b   (64 MB)
__device__ float g_W[(size_t)Bb * Tt * Dd];

// Dopri5 tableau
__constant__ float cAT[36] = {
  0,0,0,0,0,0,
  0.2f,0,0,0,0,0,
  0.075f,0.225f,0,0,0,0,
  0.9777777777777777f,-3.7333333333333334f,3.5555555555555554f,0,0,0,
  2.952598689224204f,-11.595793324188386f,9.822892851699436f,-0.2908093278463649f,0,0,
  2.8462752525252526f,-10.757575757575758f,8.906422717743473f,0.2784090909090909f,-0.27353130360205833f,0};
__constant__ float cBT[6] = {0.09114583333333333f,0.0f,0.4492362982929021f,
  0.6510416666666666f,-0.3223761792452830f,0.13095238095238096f};
// Hermite drive coefficients (t>=1): g = cFm*W[t-1] + cF0*W[t] + cFp*W[t+1]
__constant__ float cFm[6] = {0.f,-0.128f,-0.147f,-0.032f,-0.010973936899862826f,0.f};
__constant__ float cF0[6] = {1.f, 1.056f, 0.994f, 0.264f, 0.13305898491083677f,0.f};
__constant__ float cFp[6] = {0.f, 0.072f, 0.153f, 0.768f, 0.8779149519890261f, 1.f};
// t == 0 (first-point derivative copy): g = c00*W[0] + c0p*W[1]
__constant__ float c00[6] = {1.f,0.8f,0.7f,0.2f,0.1111111111111111f,0.f};
__constant__ float c0p[6] = {0.f,0.2f,0.3f,0.8f,0.8888888888888888f,1.f};

__device__ __forceinline__ ull pk2(float lo, float hi) {
    ull r; asm("mov.b64 %0,{%1,%2};" : "=l"(r) : "f"(lo), "f"(hi)); return r;
}
__device__ __forceinline__ void fma2(ull& d, ull a, ull b) {
    asm("fma.rn.f32x2 %0,%1,%2,%0;" : "+l"(d) : "l"(a), "l"(b));
}
__device__ __forceinline__ ull add2(ull a, ull b) {
    ull r; asm("add.rn.f32x2 %0,%1,%2;" : "=l"(r) : "l"(a), "l"(b)); return r;
}
__device__ __forceinline__ float red2(ull a) {
    float lo, hi; asm("mov.b64 {%0,%1},%2;" : "=f"(lo), "=f"(hi) : "l"(a)); return lo + hi;
}
__device__ __forceinline__ float tanh_f(float x) {
    float e = __expf(2.0f * x);
    return 1.0f - __fdividef(2.0f, e + 1.0f);
}

__device__ __forceinline__ float gemv256(const float* __restrict__ xbuf,
                                         const ull* __restrict__ Ash,
                                         const ull (&Ar)[NPAIR_REG], int c)
{
    const ulonglong2* xv = (const ulonglong2*)xbuf;
    ull a0 = 0, a1 = 0, a2 = 0, a3 = 0;
#pragma unroll
    for (int q = 0; q < QREG; q += 2) {
        ulonglong2 v0 = xv[q], v1 = xv[q + 1];
        fma2(a0, v0.x, Ar[2*q    ]); fma2(a1, v0.y, Ar[2*q + 1]);
        fma2(a2, v1.x, Ar[2*q + 2]); fma2(a3, v1.y, Ar[2*q + 3]);
    }
#pragma unroll
    for (int q = QREG; q < 64; q += 2) {
        ulonglong2 v0 = xv[q], v1 = xv[q + 1];
        const int p = 2*q - 2*QREG;
        fma2(a0, v0.x, Ash[(p + 0)*Dd + c]); fma2(a1, v0.y, Ash[(p + 1)*Dd + c]);
        fma2(a2, v1.x, Ash[(p + 2)*Dd + c]); fma2(a3, v1.y, Ash[(p + 3)*Dd + c]);
    }
    return red2(add2(add2(a0, a1), add2(a2, a3)));
}

// one CTA per batch element, one thread per state dim
__global__ void __launch_bounds__(256, 1)
flow_kernel(const float* __restrict__ tarr, const float* __restrict__ x0,
            const float* __restrict__ Amat, const float* __restrict__ W,
            float* __restrict__ xtraj)
{
    extern __shared__ unsigned char smraw[];
    float* xsh = (float*)smraw;               // [2][256]
    float* ksh = (float*)(smraw + 2048);      // [6][256]
    ull*   Ash = (ull*)(smraw + 8192);        // [NPAIR_SH][256]

    const int c = threadIdx.x;
    const int b = blockIdx.x;
    const float dt = tarr[1] - tarr[0];

    ull Ar[NPAIR_REG];
#pragma unroll
    for (int p = 0; p < NPAIR_REG; ++p)
        Ar[p] = pk2(Amat[(2*p)*Dd + c], Amat[(2*p + 1)*Dd + c]);
    for (int p = 0; p < NPAIR_SH; ++p)
        Ash[p*Dd + c] = pk2(Amat[(RREG + 2*p)*Dd + c], Amat[(RREG + 2*p + 1)*Dd + c]);

    float xr = x0[b*Dd + c];
    xtraj[(size_t)b*Tt*Dd + c] = xr;

    const float* Wb = W + (size_t)b*Tt*Dd;
    float w0 = Wb[c];
    float wp = Wb[Dd + c];
    float wm = 0.0f;

    __syncthreads();

    int buf = 0;
    for (int t = 0; t < Tt - 1; ++t) {
        const bool fst = (t == 0);
        for (int j = 0; j < 6; ++j) {
            float xs = xr;
            for (int i = 0; i < j; ++i)
                xs += (dt * cAT[j*6 + i]) * ksh[i*Dd + c];
            xsh[buf*Dd + c] = xs;
            __syncthreads();
            float g = fst ? (c00[j]*w0 + c0p[j]*wp)
                          : (cFm[j]*wm + cF0[j]*w0 + cFp[j]*wp);
            float kv = tanh_f(gemv256(xsh + buf*Dd, Ash, Ar, c) + g);
            ksh[j*Dd + c] = kv;
            buf ^= 1;
        }
        float acc = 0.0f;
        for (int j = 0; j < 6; ++j)
            acc += cBT[j] * ksh[j*Dd + c];
        xr += dt * acc;
        xtraj[(size_t)b*Tt*Dd + (size_t)(t + 1)*Dd + c] = xr;

        wm = w0; w0 = wp;
        if (t < Tt - 2) wp = Wb[(size_t)(t + 2)*Dd + c];
    }
}

// Out[M,N] = A[M,K] @ B[K,N] (+ bias). 64x64 tile, BK=16, 256 thr, 4x4/thread.
// M from gridDim.y*64; K%16==0, N%64==0 assumed.
__global__ void __launch_bounds__(256)
gemm_kernel(const float* __restrict__ A, const float* __restrict__ B,
            const float* __restrict__ bias, float* __restrict__ out,
            int K, int N)
{
    __shared__ float As[16][68];
    __shared__ float Bs[16][68];
    const int tid = threadIdx.x;
    const int tx = tid & 15, ty = tid >> 4;
    const int m0 = blockIdx.y * 64;
    const int n0 = blockIdx.x * 64;
    const int arow = tid >> 2, aq = tid & 3;
    const int brow = tid >> 4, bq = tid & 15;

    float acc[4][4] = {};
    for (int k0 = 0; k0 < K; k0 += 16) {
        float4 av = *(const float4*)&A[(size_t)(m0 + arow)*K + k0 + 4*aq];
        As[4*aq+0][arow] = av.x; As[4*aq+1][arow] = av.y;
        As[4*aq+2][arow] = av.z; As[4*aq+3][arow] = av.w;
        float4 bv = *(const float4*)&B[(size_t)(k0 + brow)*N + n0 + 4*bq];
        *(float4*)&Bs[brow][4*bq] = bv;
        __syncthreads();
#pragma unroll
        for (int k = 0; k < 16; ++k) {
            float a[4], bb[4];
#pragma unroll
            for (int i = 0; i < 4; ++i) a[i] = As[k][ty*4 + i];
#pragma unroll
            for (int j = 0; j < 4; ++j) bb[j] = Bs[k][tx*4 + j];
#pragma unroll
            for (int i = 0; i < 4; ++i)
#pragma unroll
                for (int j = 0; j < 4; ++j) acc[i][j] += a[i]*bb[j];
        }
        __syncthreads();
    }
#pragma unroll
    for (int i = 0; i < 4; ++i) {
        const int m = m0 + ty*4 + i;
#pragma unroll
        for (int j = 0; j < 4; ++j) {
            const int n = n0 + tx*4 + j;
            float v = acc[i][j];
            if (bias) v += bias[n];
            out[(size_t)m*N + n] = v;
        }
    }
}

extern "C" void kernel_launch(void* const* d_in, const int* in_sizes, int n_in,
                              void* d_out, int out_size)
{
    const float* tarr = (const float*)d_in[0];   // (1024,)
    const float* u    = (const float*)d_in[1];   // (64,1024,128)
    const float* x0   = (const float*)d_in[2];   // (64,256)
    const float* Amat = (const float*)d_in[3];   // (256,256)
    const float* Bm   = (const float*)d_in[4];   // (128,256)
    const float* bias = (const float*)d_in[5];   // (256,)
    const float* Cm   = (const float*)d_in[6];   // (256,64)

    float* out   = (float*)d_out;
    float* xtraj = out;                              // (64,1024,256)
    float* y     = out + (size_t)Bb * Tt * Dd;       // (64,1024,64)

    float* W = nullptr;
    cudaGetSymbolAddress((void**)&W, g_W);

    // 1) W[b,t,:] = u[b,t,:] @ Bm + bias    M=65536, K=128, N=256
    gemm_kernel<<<dim3(Dd/64, (Bb*Tt)/64), 256>>>(u, Bm, bias, W, 128, Dd);

    // 2) sequential Dopri5 flow
    cudaFuncSetAttribute(flow_kernel,
                         cudaFuncAttributeMaxDynamicSharedMemorySize, SMEM_FLOW);
    flow_kernel<<<Bb, 256, SMEM_FLOW>>>(tarr, x0, Amat, W, xtraj);

    // 3) y = x_traj @ C                     M=65536, K=256, N=64
    gemm_kernel<<<dim3(1, (Bb*Tt)/64), 256>>>(xtraj, Cm, nullptr, y, Dd, 64);
}

// round 4
// speedup vs baseline: 1.6198x; 1.6198x over previous
#include <cuda_runtime.h>
#include <cstdint>
#include <cstddef>

typedef unsigned long long ull;

#define Dd 256
#define Tt 1024
#define Bb 64
#define HALF 128

// scratch: W = u @ Bm + b   (64 MB)
__device__ float g_W[(size_t)Bb * Tt * Dd];

// Dopri5 tableau
__constant__ float cAT[36] = {
  0,0,0,0,0,0,
  0.2f,0,0,0,0,0,
  0.075f,0.225f,0,0,0,0,
  0.9777777777777777f,-3.7333333333333334f,3.5555555555555554f,0,0,0,
  2.952598689224204f,-11.595793324188386f,9.822892851699436f,-0.2908093278463649f,0,0,
  2.8462752525252526f,-10.757575757575758f,8.906422717743473f,0.2784090909090909f,-0.27353130360205833f,0};
__constant__ float cBT[6] = {0.09114583333333333f,0.0f,0.4492362982929021f,
  0.6510416666666666f,-0.3223761792452830f,0.13095238095238096f};
// Hermite drive (t>=1): g = cFm*W[t-1] + cF0*W[t] + cFp*W[t+1]
__constant__ float cFm[6] = {0.f,-0.128f,-0.147f,-0.032f,-0.010973936899862826f,0.f};
__constant__ float cF0[6] = {1.f, 1.056f, 0.994f, 0.264f, 0.13305898491083677f,0.f};
__constant__ float cFp[6] = {0.f, 0.072f, 0.153f, 0.768f, 0.8779149519890261f, 1.f};
// t == 0 (first-point derivative copy): g = c00*W[0] + c0p*W[1]
__constant__ float c00[6] = {1.f,0.8f,0.7f,0.2f,0.1111111111111111f,0.f};
__constant__ float c0p[6] = {0.f,0.2f,0.3f,0.8f,0.8888888888888888f,1.f};

// ---------------- helpers ----------------
__device__ __forceinline__ ull pk2(float lo, float hi) {
    ull r; asm("mov.b64 %0,{%1,%2};" : "=l"(r) : "f"(lo), "f"(hi)); return r;
}
__device__ __forceinline__ void fma2(ull& d, ull a, ull b) {
    asm("fma.rn.f32x2 %0,%1,%2,%0;" : "+l"(d) : "l"(a), "l"(b));
}
__device__ __forceinline__ ull add2(ull a, ull b) {
    ull r; asm("add.rn.f32x2 %0,%1,%2;" : "=l"(r) : "l"(a), "l"(b)); return r;
}
__device__ __forceinline__ float red2(ull a) {
    float lo, hi; asm("mov.b64 {%0,%1},%2;" : "=f"(lo), "=f"(hi) : "l"(a)); return lo + hi;
}
__device__ __forceinline__ float tanh_f(float x) {
    float e = __expf(2.0f * x);
    return 1.0f - __fdividef(2.0f, e + 1.0f);
}
__device__ __forceinline__ uint32_t smem_u32(const void* p) {
    uint32_t a;
    asm("{ .reg .u64 t; cvta.to.shared.u64 t, %1; cvt.u32.u64 %0, t; }"
        : "=r"(a) : "l"(p));
    return a;
}
__device__ __forceinline__ uint32_t mapa_u32(uint32_t a, uint32_t r) {
    uint32_t d; asm("mapa.shared::cluster.u32 %0, %1, %2;" : "=r"(d) : "r"(a), "r"(r));
    return d;
}
__device__ __forceinline__ void mbar_init(uint32_t a, uint32_t cnt) {
    asm volatile("mbarrier.init.shared.b64 [%0], %1;" :: "r"(a), "r"(cnt) : "memory");
}
__device__ __forceinline__ void mbar_expect_tx(uint32_t a, uint32_t bytes) {
    asm volatile("mbarrier.arrive.expect_tx.shared.b64 _, [%0], %1;"
                 :: "r"(a), "r"(bytes) : "memory");
}
__device__ __forceinline__ void bulk_s2dsm(uint32_t dst, uint32_t src,
                                           uint32_t bytes, uint32_t rbar) {
    asm volatile(
        "cp.async.bulk.shared::cluster.shared::cta.mbarrier::complete_tx::bytes "
        "[%0], [%1], %2, [%3];"
        :: "r"(dst), "r"(src), "r"(bytes), "r"(rbar) : "memory");
}
__device__ __forceinline__ void fence_proxy_async_cta() {
    asm volatile("fence.proxy.async.shared::cta;" ::: "memory");
}
__device__ __forceinline__ void wait_parity_cluster(uint32_t a, uint32_t parity) {
    asm volatile(
        "{\n\t.reg .pred P;\n\t"
        "W%=:\n\t"
        "mbarrier.try_wait.parity.acquire.cluster.shared::cta.b64 P, [%0], %1, 0x989680;\n\t"
        "@!P bra W%=;\n\t}"
        :: "r"(a), "r"(parity) : "memory");
}
__device__ __forceinline__ void cluster_sync_() {
    asm volatile("barrier.cluster.arrive.aligned;" ::: "memory");
    asm volatile("barrier.cluster.wait.aligned;" ::: "memory");
}

// ================ sequential Dopri5 flow ================
// Cluster of 2 CTAs per batch element; column split (128 cols per CTA).
// 256 threads: col = rank*128 + (tid&127), row-half h = tid>>7.
// A column-slice fully register-resident: 64 packed f32x2 pairs = 128 regs.
__global__ void __launch_bounds__(256, 1) __cluster_dims__(2, 1, 1)
flow_kernel(const float* __restrict__ tarr, const float* __restrict__ x0,
            const float* __restrict__ Amat, const float* __restrict__ W,
            float* __restrict__ xtraj)
{
    __shared__ __align__(16) float xsh[Dd];       // full state vector
    __shared__ float psh[HALF];                   // row-half partials
    __shared__ __align__(16) float ksh[6 * Dd];   // k per stage, both halves
    __shared__ __align__(8)  ull  mbar[6];        // exchange barriers (1 per stage slot)

    const int tid = threadIdx.x;
    const int lc  = tid & (HALF - 1);
    const int h   = tid >> 7;
    uint32_t rank; asm("mov.u32 %0, %%cluster_ctarank;" : "=r"(rank));
    const uint32_t peer = rank ^ 1u;
    const int b   = blockIdx.x >> 1;
    const int col = (int)rank * HALF + lc;
    const float dt = tarr[1] - tarr[0];

    const uint32_t ksh_a  = smem_u32(ksh);
    const uint32_t mbar_a = smem_u32(mbar);

    if (tid == 0)
        for (int j = 0; j < 6; ++j) mbar_init(mbar_a + 8u*j, 1);
    __syncthreads();
    cluster_sync_();   // barriers visible cluster-wide before any exchange

    // load A column slice (rows [h*128, h*128+128), column col) into registers
    ull Ar[64];
#pragma unroll
    for (int p = 0; p < 64; ++p)
        Ar[p] = pk2(Amat[(h*HALF + 2*p)*Dd + col],
                    Amat[(h*HALF + 2*p + 1)*Dd + col]);

    float xr = x0[b*Dd + tid];                 // full state kept in every CTA
    if (h == (int)rank)
        xtraj[(size_t)b*Tt*Dd + tid] = xr;     // each CTA writes its column half

    const float* Wb = W + (size_t)b*Tt*Dd + col;
    float w0 = 0.f, wp = 0.f, wm = 0.f;
    if (h == 0) { w0 = Wb[0]; wp = Wb[Dd]; }

    for (int t = 0; t < Tt - 1; ++t) {
        const uint32_t par = (uint32_t)(t & 1);
        const bool fst = (t == 0);
        float acc04 = 0.0f;                    // sum_{j<=4} bT_j * k_j  (pre-read, see below)

#pragma unroll 1
        for (int j = 0; j < 6; ++j) {
            // stage state xs = xr + dt * sum_i a_ji k_i   (k halves already exchanged)
            float xs = xr;
            for (int i = 0; i < j; ++i)
                xs += (dt * cAT[j*6 + i]) * ksh[i*Dd + tid];
            xsh[tid] = xs;
            __syncthreads();

            // 128-row dot for this thread's column (all-register A, broadcast x)
            const ulonglong2* xv = (const ulonglong2*)(xsh + h*HALF);
            ull a0 = 0, a1 = 0, a2 = 0, a3 = 0;
#pragma unroll
            for (int q = 0; q < 32; q += 2) {
                ulonglong2 v0 = xv[q], v1 = xv[q + 1];
                fma2(a0, v0.x, Ar[2*q    ]); fma2(a1, v0.y, Ar[2*q + 1]);
                fma2(a2, v1.x, Ar[2*q + 2]); fma2(a3, v1.y, Ar[2*q + 3]);
            }
            float part = red2(add2(add2(a0, a1), add2(a2, a3)));

            if (h == 1) psh[lc] = part;
            __syncthreads();
            if (h == 0) {
                float g = fst ? (c00[j]*w0 + c0p[j]*wp)
                              : (cFm[j]*wm + cF0[j]*w0 + cFp[j]*wp);
                ksh[j*Dd + col] = tanh_f(part + psh[lc] + g);
            }
            if (j == 5) {
                // hoist b-weight partial sum over k0..k4 BEFORE the pre-copy bar:
                // makes slot-0 buffer reuse at step t+1 formally ordered.
                acc04 = cBT[0]*ksh[0*Dd + tid] + cBT[2]*ksh[2*Dd + tid]
                      + cBT[3]*ksh[3*Dd + tid] + cBT[4]*ksh[4*Dd + tid];
            }
            __syncthreads();

            // exchange this CTA's k-half with the peer (512 B DSMEM bulk copy)
            if (tid == 0) {
                fence_proxy_async_cta();
                mbar_expect_tx(mbar_a + 8u*j, HALF*4);       // receive side
                uint32_t src = ksh_a + (uint32_t)(j*Dd + (int)rank*HALF)*4u;
                bulk_s2dsm(mapa_u32(src, peer), src, HALF*4,
                           mapa_u32(mbar_a + 8u*j, peer));
            }
            wait_parity_cluster(mbar_a + 8u*j, par);
        }

        xr += dt * (acc04 + cBT[5]*ksh[5*Dd + tid]);
        if (h == (int)rank)
            xtraj[(size_t)b*Tt*Dd + (size_t)(t + 1)*Dd + tid] = xr;

        if (h == 0) {
            wm = w0; w0 = wp;
            if (t < Tt - 2) wp = Wb[(size_t)(t + 2)*Dd];
        }
    }
}

// Out[M,N] = A[M,K] @ B[K,N] (+ bias). 64x64 tile, BK=16, 256 thr, 4x4/thread.
__global__ void __launch_bounds__(256)
gemm_kernel(const float* __restrict__ A, const float* __restrict__ B,
            const float* __restrict__ bias, float* __restrict__ out,
            int K, int N)
{
    __shared__ float As[16][68];
    __shared__ float Bs[16][68];
    const int tid = threadIdx.x;
    const int tx = tid & 15, ty = tid >> 4;
    const int m0 = blockIdx.y * 64;
    const int n0 = blockIdx.x * 64;
    const int arow = tid >> 2, aq = tid & 3;
    const int brow = tid >> 4, bq = tid & 15;

    float acc[4][4] = {};
    for (int k0 = 0; k0 < K; k0 += 16) {
        float4 av = *(const float4*)&A[(size_t)(m0 + arow)*K + k0 + 4*aq];
        As[4*aq+0][arow] = av.x; As[4*aq+1][arow] = av.y;
        As[4*aq+2][arow] = av.z; As[4*aq+3][arow] = av.w;
        float4 bv = *(const float4*)&B[(size_t)(k0 + brow)*N + n0 + 4*bq];
        *(float4*)&Bs[brow][4*bq] = bv;
        __syncthreads();
#pragma unroll
        for (int k = 0; k < 16; ++k) {
            float a[4], bb[4];
#pragma unroll
            for (int i = 0; i < 4; ++i) a[i] = As[k][ty*4 + i];
#pragma unroll
            for (int jj = 0; jj < 4; ++jj) bb[jj] = Bs[k][tx*4 + jj];
#pragma unroll
            for (int i = 0; i < 4; ++i)
#pragma unroll
                for (int jj = 0; jj < 4; ++jj) acc[i][jj] += a[i]*bb[jj];
        }
        __syncthreads();
    }
#pragma unroll
    for (int i = 0; i < 4; ++i) {
        const int m = m0 + ty*4 + i;
#pragma unroll
        for (int jj = 0; jj < 4; ++jj) {
            const int n = n0 + tx*4 + jj;
            float v = acc[i][jj];
            if (bias) v += bias[n];
            out[(size_t)m*N + n] = v;
        }
    }
}

extern "C" void kernel_launch(void* const* d_in, const int* in_sizes, int n_in,
                              void* d_out, int out_size)
{
    const float* tarr = (const float*)d_in[0];   // (1024,)
    const float* u    = (const float*)d_in[1];   // (64,1024,128)
    const float* x0   = (const float*)d_in[2];   // (64,256)
    const float* Amat = (const float*)d_in[3];   // (256,256)
    const float* Bm   = (const float*)d_in[4];   // (128,256)
    const float* bias = (const float*)d_in[5];   // (256,)
    const float* Cm   = (const float*)d_in[6];   // (256,64)

    float* out   = (float*)d_out;
    float* xtraj = out;                              // (64,1024,256)
    float* y     = out + (size_t)Bb * Tt * Dd;       // (64,1024,64)

    float* W = nullptr;
    cudaGetSymbolAddress((void**)&W, g_W);

    // 1) W[b,t,:] = u[b,t,:] @ Bm + bias    M=65536, K=128, N=256
    gemm_kernel<<<dim3(Dd/64, (Bb*Tt)/64), 256>>>(u, Bm, bias, W, 128, Dd);

    // 2) sequential Dopri5 flow: 64 batches x 2-CTA clusters = 128 CTAs
    flow_kernel<<<2*Bb, 256>>>(tarr, x0, Amat, W, xtraj);

    // 3) y = x_traj @ C                     M=65536, K=256, N=64
    gemm_kernel<<<dim3(1, (Bb*Tt)/64), 256>>>(xtraj, Cm, nullptr, y, Dd, 64);
}